// round 15
// baseline (speedup 1.0000x reference)
#include <cuda_runtime.h>
#include <cstdint>

#define TOKENS 65536
#define KCODES 1024
#define DDIM   64
#define HW     4096
#define TM     128
#define TN     128
#define NCH    (KCODES / TN)

#define FRAG_U4   (8 * 16 * 32)            // per chunk: 4096 uint4 (bh|bl interleaved)
#define FRAG_B    (FRAG_U4 * 16)           // 65536 B
#define HNP_B     512                      // 64 float2 pairs (negated half-norms)

#define SM_IDX 0
#define SM_ALO 512                          // 8 warps x 8 s x 32 lanes x 16B = 32 KB
#define SM_BUF (SM_ALO + 32768)
#define SM_HNP (SM_BUF + FRAG_B)
#define SMEM_TOTAL (SM_HNP + HNP_B)         // 99328 B -> 2 CTAs/SM

__device__ uint4  g_bfr[NCH * FRAG_U4];     // fragment-ordered: {bh0,bh1,bl0,bl1}
__device__ float2 g_hnp[NCH * 64];          // (-0.5|c|^2, -0.5|c_+1|^2) per (j,tig)

__device__ __forceinline__ uint32_t f2tf32(float v) {
    uint32_t r; asm("cvt.rna.tf32.f32 %0, %1;" : "=r"(r) : "f"(v)); return r;
}

// One-shot prep: codebook -> interleaved tf32 hi/lo fragments + negated norm pairs.
__global__ void vq_prep(const float* __restrict__ cb) {
    int idx = blockIdx.x * 256 + threadIdx.x;
    if (idx < 512) {                         // hnp entries: ch = idx>>6, pair = idx&63
        int ch = idx >> 6, pe = idx & 63;
        int j = pe >> 2, tig = pe & 3;
        int c = ch * TN + j * 8 + tig * 2;
        float s0 = 0.f, s1 = 0.f;
        #pragma unroll 8
        for (int k = 0; k < DDIM; ++k) {
            float a = cb[c * DDIM + k], b = cb[(c + 1) * DDIM + k];
            s0 += a * a; s1 += b * b;
        }
        g_hnp[ch * 64 + pe] = make_float2(-0.5f * s0, -0.5f * s1);
    } else if (idx < 512 + NCH * TN * DDIM) {
        int f = idx - 512;
        int ch = f >> 13, rem = f & 8191;
        int n = rem >> 6, k = rem & 63;
        float v = cb[(ch * TN + n) * DDIM + k];
        uint32_t hi = f2tf32(v);
        uint32_t lo = f2tf32(v - __uint_as_float(hi));
        int s = k >> 3, j = n >> 3;
        int ln = (n & 7) * 4 + (k & 3), half = (k >> 2) & 1;
        uint32_t* base = (uint32_t*)(g_bfr + (ch * 128 + s * 16 + j) * 32 + ln);
        base[half] = hi;
        base[2 + half] = lo;
    }
}

#define MMA(d, a0, a1, a2, a3, b0, b1)                                        \
    asm("mma.sync.aligned.m16n8k8.row.col.f32.tf32.tf32.f32 "                 \
        "{%0,%1,%2,%3}, {%4,%5,%6,%7}, {%8,%9}, {%0,%1,%2,%3};"               \
        : "+f"((d)[0]), "+f"((d)[1]), "+f"((d)[2]), "+f"((d)[3])              \
        : "r"(a0), "r"(a1), "r"(a2), "r"(a3), "r"(b0), "r"(b1))

#define CP16(dst, src) \
    asm volatile("cp.async.cg.shared.global [%0], [%1], 16;" \
                 :: "r"(dst), "l"(src) : "memory")

#define BETTER(v, c, bv, bi) \
    if ((v) > (bv) || ((v) == (bv) && (c) < (bi))) { (bv) = (v); (bi) = (c); }

// Main: occ 2; split-group cp.async staging (mma overlaps 2nd half);
// acc init from -hn pairs (no norm kstep); chunk order staggered per SM pair.
__global__ __launch_bounds__(256, 2)
void vq_tc(const float* __restrict__ inp, const float* __restrict__ cb,
           float* __restrict__ out, int out_size) {
    extern __shared__ char smem[];
    int*   sidx = (int*)(smem + SM_IDX);
    float* araw = (float*)(smem + SM_BUF);      // [128][65] transient A staging
    uint32_t sbase = (uint32_t)__cvta_generic_to_shared(smem);

    int tid = threadIdx.x, wid = tid >> 5, lane = tid & 31;
    int gid = lane >> 2, tig = lane & 3;
    int n0 = blockIdx.x * TM;
    int b = n0 >> 12, s0 = n0 & (HW - 1);
    const float* ibase = inp + (long long)b * DDIM * HW + s0;

    for (int e = tid; e < TM * DDIM; e += 256) {
        int t = e & 127, d = e >> 7;
        araw[t * 65 + d] = ibase[d * HW + t];
    }
    __syncthreads();

    int r0 = wid * 16 + gid, r1 = r0 + 8;
    uint32_t ahi[8][4];
    #pragma unroll
    for (int s = 0; s < 8; ++s) {               // ahi -> regs, alo -> per-warp smem
        float v[4] = { araw[r0 * 65 + s * 8 + tig],     araw[r1 * 65 + s * 8 + tig],
                       araw[r0 * 65 + s * 8 + tig + 4], araw[r1 * 65 + s * 8 + tig + 4] };
        uint32_t lo[4];
        #pragma unroll
        for (int i = 0; i < 4; ++i) {
            ahi[s][i] = f2tf32(v[i]);
            lo[i] = f2tf32(v[i] - __uint_as_float(ahi[s][i]));
        }
        uint32_t dst = sbase + SM_ALO + wid * 4096 + (s * 32 + lane) * 16;
        asm volatile("st.shared.v4.b32 [%0], {%1,%2,%3,%4};"
                     :: "r"(dst), "r"(lo[0]), "r"(lo[1]), "r"(lo[2]), "r"(lo[3])
                     : "memory");
    }
    __syncthreads();                             // araw dead; buffer reusable

    float best0 = -3.4e38f, best1 = -3.4e38f;
    int bi0 = 0, bi1 = 0;
    uint32_t alo_base = sbase + SM_ALO + wid * 4096 + lane * 16;
    int rot = ((blockIdx.x / 148) & 1) * 4;      // de-phase co-resident CTAs

    for (int chi = 0; chi < NCH; ++chi) {
        int ch = (chi + rot) & (NCH - 1);
        int c0 = ch * TN;

        // Group A: hnp + ksteps 0..3 (first 2048 uint4); Group B: ksteps 4..7
        {
            uint32_t dst = sbase + SM_BUF;
            const char* src = (const char*)(g_bfr + ch * FRAG_U4);
            #pragma unroll
            for (int i = 0; i < 8; ++i)
                CP16(dst + (tid + i * 256) * 16, src + (tid + i * 256) * 16);
            if (tid < 32)
                CP16(sbase + SM_HNP + tid * 16,
                     (const char*)(g_hnp + ch * 64) + tid * 16);
            asm volatile("cp.async.commit_group;" ::: "memory");
            #pragma unroll
            for (int i = 8; i < 16; ++i)
                CP16(dst + (tid + i * 256) * 16, src + (tid + i * 256) * 16);
            asm volatile("cp.async.commit_group;" ::: "memory");
            asm volatile("cp.async.wait_group 1;" ::: "memory");
        }
        __syncthreads();                         // half A + hnp staged

        const uint4* frag = (const uint4*)(smem + SM_BUF) + lane;
        const float2* hnp = (const float2*)(smem + SM_HNP);

        float acc[16][4];
        #pragma unroll
        for (int j = 0; j < 16; ++j) {           // init = -0.5|c|^2 (replaces norm kstep)
            float2 h = hnp[j * 4 + tig];
            acc[j][0] = h.x; acc[j][1] = h.y;
            acc[j][2] = h.x; acc[j][3] = h.y;
        }

        #pragma unroll
        for (int s = 0; s < 4; ++s) {
            uint32_t al[4];
            asm volatile("ld.shared.v4.b32 {%0,%1,%2,%3}, [%4];"
                         : "=r"(al[0]), "=r"(al[1]), "=r"(al[2]), "=r"(al[3])
                         : "r"(alo_base + s * 512));
            #pragma unroll
            for (int j = 0; j < 16; ++j) {
                uint4 bf = frag[(s * 16 + j) * 32];
                MMA(acc[j], ahi[s][0], ahi[s][1], ahi[s][2], ahi[s][3], bf.x, bf.y);
                MMA(acc[j], ahi[s][0], ahi[s][1], ahi[s][2], ahi[s][3], bf.z, bf.w);
                MMA(acc[j], al[0], al[1], al[2], al[3], bf.x, bf.y);
            }
        }

        asm volatile("cp.async.wait_group 0;" ::: "memory");
        __syncthreads();                         // half B staged

        #pragma unroll
        for (int s = 4; s < 8; ++s) {
            uint32_t al[4];
            asm volatile("ld.shared.v4.b32 {%0,%1,%2,%3}, [%4];"
                         : "=r"(al[0]), "=r"(al[1]), "=r"(al[2]), "=r"(al[3])
                         : "r"(alo_base + s * 512));
            #pragma unroll
            for (int j = 0; j < 16; ++j) {
                uint4 bf = frag[(s * 16 + j) * 32];
                MMA(acc[j], ahi[s][0], ahi[s][1], ahi[s][2], ahi[s][3], bf.x, bf.y);
                MMA(acc[j], ahi[s][0], ahi[s][1], ahi[s][2], ahi[s][3], bf.z, bf.w);
                MMA(acc[j], al[0], al[1], al[2], al[3], bf.x, bf.y);
            }
        }

        // Running argmax with exact lowest-index tie-break (chunk order is rotated)
        #pragma unroll
        for (int j = 0; j < 16; ++j) {
            int colb = c0 + j * 8 + tig * 2;
            BETTER(acc[j][0], colb,     best0, bi0);
            BETTER(acc[j][1], colb + 1, best0, bi0);
            BETTER(acc[j][2], colb,     best1, bi1);
            BETTER(acc[j][3], colb + 1, best1, bi1);
        }
        __syncthreads();                         // all warps done before restage
    }

    // Quad reduce (lanes differing in tig hold different columns)
    #pragma unroll
    for (int m = 1; m <= 2; m <<= 1) {
        float ov; int oi;
        ov = __shfl_xor_sync(0xffffffffu, best0, m);
        oi = __shfl_xor_sync(0xffffffffu, bi0, m);
        if (ov > best0 || (ov == best0 && oi < bi0)) { best0 = ov; bi0 = oi; }
        ov = __shfl_xor_sync(0xffffffffu, best1, m);
        oi = __shfl_xor_sync(0xffffffffu, bi1, m);
        if (ov > best1 || (ov == best1 && oi < bi1)) { best1 = ov; bi1 = oi; }
    }
    if (tig == 0) { sidx[r0] = bi0; sidx[r1] = bi1; }
    __syncthreads();

    // Fused gather: out[b][d][s0+t] = cb[idx[t]][d]; coalesced writes, L2-hot reads.
    for (int e = tid; e < TM * DDIM; e += 256) {
        int d = e >> 7, t = e & 127;
        out[((long long)b * DDIM + d) * HW + s0 + t] = cb[sidx[t] * DDIM + d];
    }
    if (out_size > TOKENS * DDIM && tid < TM)
        out[TOKENS * DDIM + n0 + tid] = (float)sidx[tid];
}

extern "C" void kernel_launch(void* const* d_in, const int* in_sizes, int n_in,
                              void* d_out, int out_size) {
    const float* inp = (const float*)d_in[0];   // (16, 64, 64, 64) f32
    const float* cb  = (const float*)d_in[1];   // (1024, 64) f32
    float* out = (float*)d_out;

    cudaFuncSetAttribute(vq_tc, cudaFuncAttributeMaxDynamicSharedMemorySize, SMEM_TOTAL);

    vq_prep<<<(512 + NCH * TN * DDIM + 255) / 256, 256>>>(cb);
    vq_tc<<<TOKENS / TM, 256, SMEM_TOTAL>>>(inp, cb, out, out_size);
}